// round 14
// baseline (speedup 1.0000x reference)
#include <cuda_runtime.h>
#include <cuda_bf16.h>
#include <cfloat>
#include <cstdint>

// LossFun: loss = -sum over (b,l) of [argmax_v(scores)==target] * w * log(max score) / B
// scores: [B, L, V] float32, targets: [B, L] int32. B=8, L=2048, V=32000.
//
// R14: split each row across 2 CTAs (64KB quantum) to halve wave-tail
// quantization (13.47 waves of 21us CTAs -> 26.9 waves of 10.5us CTAs).
// Halves write (max, idx) to static scratch; a single-CTA combine kernel
// merges pairs, applies the match/weight/log, block-reduces in double and
// writes out directly — no global accumulator, no atomics, no resets.
//
// Scan per half: FMNMX-tree fast path, rare index-resolution slow path on
// running-best improvement only. Strict '>' + in-order resolution, and
// 'm0 >= m1' at combine, preserve argmax first-index tiebreak.
//
// Precision: picked ~ (1 - 3e-5) -> log(picked) ~ -3e-5: accurate logf +
// double block-reduce (rel_err ~2e-7).

static constexpr int V_DIM   = 32000;
static constexpr int V_HALF  = V_DIM / 2;      // 16000 floats
static constexpr int HV4     = V_HALF / 4;     // 4000 vec4
static constexpr int MAX_ROWS = 16384;
static constexpr double INV_B = 1.0 / 8.0;
static constexpr float  BETA  = 2.0f;

__device__ float g_max[MAX_ROWS * 2];
__device__ int   g_idx[MAX_ROWS * 2];

__device__ __forceinline__ void tile_update(const float4& v, int base,
                                            int& bidx, float m)
{
    if (v.x == m && base + 0 < bidx) { bidx = base + 0; return; }
    if (v.y == m && base + 1 < bidx) { bidx = base + 1; return; }
    if (v.z == m && base + 2 < bidx) { bidx = base + 2; return; }
    if (v.w == m && base + 3 < bidx) { bidx = base + 3; return; }
}

__global__ __launch_bounds__(256, 4)
void lossfun_halfmax_kernel(const float* __restrict__ scores)
{
    const int tid  = threadIdx.x;
    const int slot = blockIdx.x;          // row*2 + half
    const int row  = slot >> 1;
    const int half = slot & 1;

    const float4* __restrict__ p = reinterpret_cast<const float4*>(
        scores + (size_t)row * V_DIM + half * V_HALF);
    const int ebase = half * V_HALF;      // global element offset of this half

    float best = -FLT_MAX;
    int   bidx = 0x7FFFFFFF;

    // Main loop: 3 iterations x 4 coalesced float4 loads = 3072 vec4.
    #pragma unroll
    for (int k = 0; k < 3; k++) {
        const int i = tid + k * 1024;
        float4 a = __ldg(p + i);
        float4 b = __ldg(p + i + 256);
        float4 c = __ldg(p + i + 512);
        float4 d = __ldg(p + i + 768);

        float ma = fmaxf(fmaxf(a.x, a.y), fmaxf(a.z, a.w));
        float mb = fmaxf(fmaxf(b.x, b.y), fmaxf(b.z, b.w));
        float mc = fmaxf(fmaxf(c.x, c.y), fmaxf(c.z, c.w));
        float md = fmaxf(fmaxf(d.x, d.y), fmaxf(d.z, d.w));
        float m  = fmaxf(fmaxf(ma, mb), fmaxf(mc, md));

        if (m > best) {                   // rare
            best = m;
            bidx = 0x7FFFFFFF;
            if      (ma == m) tile_update(a, ebase + ((i)        << 2), bidx, m);
            if (bidx == 0x7FFFFFFF && mb == m) tile_update(b, ebase + ((i + 256) << 2), bidx, m);
            if (bidx == 0x7FFFFFFF && mc == m) tile_update(c, ebase + ((i + 512) << 2), bidx, m);
            if (bidx == 0x7FFFFFFF && md == m) tile_update(d, ebase + ((i + 768) << 2), bidx, m);
        }
    }

    // Epilogue: vec4 3072..3999 (928 = 3*256 + 160).
    {
        const int i1 = 3072 + tid;
        const int i2 = 3328 + tid;
        const int i3 = 3584 + tid;
        float4 a = __ldg(p + i1);
        float4 b = __ldg(p + i2);
        float4 c = __ldg(p + i3);

        float ma = fmaxf(fmaxf(a.x, a.y), fmaxf(a.z, a.w));
        float mb = fmaxf(fmaxf(b.x, b.y), fmaxf(b.z, b.w));
        float mc = fmaxf(fmaxf(c.x, c.y), fmaxf(c.z, c.w));
        float m  = fmaxf(fmaxf(ma, mb), mc);

        if (m > best) {
            best = m;
            bidx = 0x7FFFFFFF;
            if      (ma == m) tile_update(a, ebase + (i1 << 2), bidx, m);
            if (bidx == 0x7FFFFFFF && mb == m) tile_update(b, ebase + (i2 << 2), bidx, m);
            if (bidx == 0x7FFFFFFF && mc == m) tile_update(c, ebase + (i3 << 2), bidx, m);
        }

        if (tid < 160) {
            const int i4 = 3840 + tid;
            float4 d = __ldg(p + i4);
            float md = fmaxf(fmaxf(d.x, d.y), fmaxf(d.z, d.w));
            if (md > best) {
                best = md;
                bidx = 0x7FFFFFFF;
                tile_update(d, ebase + (i4 << 2), bidx, md);
            }
        }
    }

    // Warp reduce (value-max, lowest index on tie)
    #pragma unroll
    for (int o = 16; o > 0; o >>= 1) {
        float ov = __shfl_down_sync(0xFFFFFFFFu, best, o);
        int   oi = __shfl_down_sync(0xFFFFFFFFu, bidx, o);
        if (ov > best || (ov == best && oi < bidx)) { best = ov; bidx = oi; }
    }

    __shared__ float sv[8];
    __shared__ int   si[8];
    const int lane = tid & 31;
    const int wid  = tid >> 5;
    if (lane == 0) { sv[wid] = best; si[wid] = bidx; }
    __syncthreads();

    if (tid == 0) {
        float fb = sv[0]; int fi = si[0];
        #pragma unroll
        for (int w = 1; w < 8; w++) {
            float ov = sv[w]; int oi = si[w];
            if (ov > fb || (ov == fb && oi < fi)) { fb = ov; fi = oi; }
        }
        g_max[slot] = fb;
        g_idx[slot] = fi;
    }
}

__global__ __launch_bounds__(1024, 1)
void lossfun_combine_kernel(const int* __restrict__ targets,
                            float* __restrict__ out,
                            int rows)
{
    const int tid = threadIdx.x;
    double sum = 0.0;

    for (int r = tid; r < rows; r += 1024) {
        float m0 = g_max[2 * r];     int i0 = g_idx[2 * r];
        float m1 = g_max[2 * r + 1]; int i1 = g_idx[2 * r + 1];
        // lower-index half wins ties -> >=
        float fb = (m0 >= m1) ? m0 : m1;
        int   fi = (m0 >= m1) ? i0 : i1;
        int   tgt = __ldg(targets + r);
        if (fi == tgt) {
            float w = (tgt == 0) ? 1.0f : BETA;
            sum += (double)(-w * logf(fb));
        }
    }

    // Block reduce (double) via warp shuffles + shared.
    #pragma unroll
    for (int o = 16; o > 0; o >>= 1)
        sum += __shfl_down_sync(0xFFFFFFFFu, sum, o);

    __shared__ double ssum[32];
    const int lane = tid & 31;
    const int wid  = tid >> 5;
    if (lane == 0) ssum[wid] = sum;
    __syncthreads();

    if (wid == 0) {
        double s = (lane < 32) ? ssum[lane] : 0.0;
        #pragma unroll
        for (int o = 16; o > 0; o >>= 1)
            s += __shfl_down_sync(0xFFFFFFFFu, s, o);
        if (lane == 0) out[0] = (float)(s * INV_B);
    }
}

extern "C" void kernel_launch(void* const* d_in, const int* in_sizes, int n_in,
                              void* d_out, int out_size)
{
    const float* scores  = (const float*)d_in[0];
    const int*   targets = (const int*)d_in[1];
    float*       out     = (float*)d_out;

    const int rows = in_sizes[1];   // B * L = 16384 (<= MAX_ROWS)

    lossfun_halfmax_kernel<<<rows * 2, 256>>>(scores);
    lossfun_combine_kernel<<<1, 1024>>>(targets, out, rows);
}

// round 16
// speedup vs baseline: 1.0454x; 1.0454x over previous
#include <cuda_runtime.h>
#include <cuda_bf16.h>
#include <cfloat>
#include <cstdint>

// LossFun: loss = -sum over (b,l) of [argmax_v(scores)==target] * w * log(max score) / B
// scores: [B, L, V] float32, targets: [B, L] int32. B=8, L=2048, V=32000.
//
// FINAL. One CTA per row streaming argmax (~7.4 TB/s, 92-94% of HBM spec) +
// double g_acc atomic per matched row + 1-thread finalize kernel (writes out,
// resets g_acc for graph-replay determinism). Score loads use __ldcs
// (evict-first streaming): data is read exactly once, so no L2 residency.
//
// Measured dead ends (14 rounds, do not revisit):
//  - last-CTA fusion w/ __threadfence (R6): +7.5us;
//  - last-CTA fusion w/ atom.add.acq_rel counter (R9): +10us;
//  - float atomic straight to d_out + memset (R8): parity, less margin;
//  - persistent 1216-CTA grid-stride (R12): +25us (per-row barrier
//    serializes the load stream; HW work-stealing already hides waves);
//  - 2-CTA row split + combine kernel (R14): main unchanged (tail already
//    hidden), combine +12us on DRAM-cold scratch.
//
// Scan: FMNMX-tree fast path (tile max, ~1.5 instrs/float), rare index
// resolution only on running-best improvement (~ln(#tiles)/thread).
// Strict '>' + in-order resolution preserves argmax first-index tiebreak.
//
// Precision: picked = max of 32000 uniforms ~ (1 - 3e-5), log(picked) ~ -3e-5:
// accurate logf (NOT __logf) + double accumulator -> rel_err 2.3e-7.

static constexpr int V_DIM  = 32000;
static constexpr double INV_B = 1.0 / 8.0;
static constexpr float  BETA  = 2.0f;

__device__ double g_acc;   // zero-init at module load; finalize resets per replay

__device__ __forceinline__ void tile_update(const float4& v, int base,
                                            int& bidx, float m)
{
    if (v.x == m && base + 0 < bidx) { bidx = base + 0; return; }
    if (v.y == m && base + 1 < bidx) { bidx = base + 1; return; }
    if (v.z == m && base + 2 < bidx) { bidx = base + 2; return; }
    if (v.w == m && base + 3 < bidx) { bidx = base + 3; return; }
}

__global__ __launch_bounds__(256, 4)
void lossfun_argmax_kernel(const float* __restrict__ scores,
                           const int* __restrict__ targets)
{
    const int tid = threadIdx.x;
    const int row = blockIdx.x;
    const float4* __restrict__ p =
        reinterpret_cast<const float4*>(scores + (size_t)row * V_DIM);

    float best = -FLT_MAX;
    int   bidx = 0x7FFFFFFF;

    // Main loop: 7 iterations x 4 coalesced streaming float4 loads.
    #pragma unroll
    for (int k = 0; k < 7; k++) {
        const int i = tid + k * 1024;
        float4 a = __ldcs(p + i);
        float4 b = __ldcs(p + i + 256);
        float4 c = __ldcs(p + i + 512);
        float4 d = __ldcs(p + i + 768);

        float ma = fmaxf(fmaxf(a.x, a.y), fmaxf(a.z, a.w));
        float mb = fmaxf(fmaxf(b.x, b.y), fmaxf(b.z, b.w));
        float mc = fmaxf(fmaxf(c.x, c.y), fmaxf(c.z, c.w));
        float md = fmaxf(fmaxf(d.x, d.y), fmaxf(d.z, d.w));
        float m  = fmaxf(fmaxf(ma, mb), fmaxf(mc, md));

        if (m > best) {                 // rare: ~ln(#tiles) per thread
            best = m;
            bidx = 0x7FFFFFFF;
            if      (ma == m) tile_update(a, (i)          << 2, bidx, m);
            if (bidx == 0x7FFFFFFF && mb == m) tile_update(b, (i + 256) << 2, bidx, m);
            if (bidx == 0x7FFFFFFF && mc == m) tile_update(c, (i + 512) << 2, bidx, m);
            if (bidx == 0x7FFFFFFF && md == m) tile_update(d, (i + 768) << 2, bidx, m);
        }
    }

    // Epilogue: vec4 indices 7168..7999 (832 = 3*256 + 64).
    {
        const int i1 = 7168 + tid;
        const int i2 = 7424 + tid;
        const int i3 = 7680 + tid;
        float4 a = __ldcs(p + i1);
        float4 b = __ldcs(p + i2);
        float4 c = __ldcs(p + i3);

        float ma = fmaxf(fmaxf(a.x, a.y), fmaxf(a.z, a.w));
        float mb = fmaxf(fmaxf(b.x, b.y), fmaxf(b.z, b.w));
        float mc = fmaxf(fmaxf(c.x, c.y), fmaxf(c.z, c.w));
        float m  = fmaxf(fmaxf(ma, mb), mc);

        if (m > best) {
            best = m;
            bidx = 0x7FFFFFFF;
            if      (ma == m) tile_update(a, i1 << 2, bidx, m);
            if (bidx == 0x7FFFFFFF && mb == m) tile_update(b, i2 << 2, bidx, m);
            if (bidx == 0x7FFFFFFF && mc == m) tile_update(c, i3 << 2, bidx, m);
        }

        if (tid < 64) {
            const int i4 = 7936 + tid;
            float4 d = __ldcs(p + i4);
            float md = fmaxf(fmaxf(d.x, d.y), fmaxf(d.z, d.w));
            if (md > best) {
                best = md;
                bidx = 0x7FFFFFFF;
                tile_update(d, i4 << 2, bidx, md);
            }
        }
    }

    // Warp reduce (value-max, lowest index on tie)
    #pragma unroll
    for (int o = 16; o > 0; o >>= 1) {
        float ov = __shfl_down_sync(0xFFFFFFFFu, best, o);
        int   oi = __shfl_down_sync(0xFFFFFFFFu, bidx, o);
        if (ov > best || (ov == best && oi < bidx)) { best = ov; bidx = oi; }
    }

    __shared__ float sv[8];
    __shared__ int   si[8];
    const int lane = tid & 31;
    const int wid  = tid >> 5;
    if (lane == 0) { sv[wid] = best; si[wid] = bidx; }
    __syncthreads();

    if (tid == 0) {
        float fb = sv[0]; int fi = si[0];
        #pragma unroll
        for (int w = 1; w < 8; w++) {
            float ov = sv[w]; int oi = si[w];
            if (ov > fb || (ov == fb && oi < fi)) { fb = ov; fi = oi; }
        }
        int tgt = __ldg(targets + row);
        if (fi == tgt) {
            float w = (tgt == 0) ? 1.0f : BETA;
            atomicAdd(&g_acc, (double)(-w * logf(fb)));
        }
    }
}

__global__ void lossfun_finalize_kernel(float* __restrict__ out)
{
    out[0] = (float)(g_acc * INV_B);
    g_acc  = 0.0;   // restore invariant for next graph replay
}

extern "C" void kernel_launch(void* const* d_in, const int* in_sizes, int n_in,
                              void* d_out, int out_size)
{
    const float* scores  = (const float*)d_in[0];
    const int*   targets = (const int*)d_in[1];
    float*       out     = (float*)d_out;

    const int rows = in_sizes[1];   // B * L = 16384

    lossfun_argmax_kernel<<<rows, 256>>>(scores, targets);
    lossfun_finalize_kernel<<<1, 1>>>(out);
}